// round 1
// baseline (speedup 1.0000x reference)
#include <cuda_runtime.h>

// Problem constants
#define B_   16
#define D_   448
#define HW_  4096
#define DSQ  (D_*D_)              // 200704
#define NOUT (16L*448L*4096L)     // 29360128 elements of c_i, loss at [NOUT]
#define NPART 7168                // 7*64*16 loss partials

// Scratch (module globals — allocation-free rule)
__device__ float g_G[32L*DSQ];   // gram: [0..15]=pos, [16..31]=neg
__device__ float g_T[32L*DSQ];   // G @ Wk^T
__device__ float g_S[32L*DSQ];   // scores -> alpha (in place)
__device__ float g_A[32L*DSQ];   // alpha @ Wv
__device__ float g_part[NPART];

// ---- packed fp32x2 helpers (B300: scalar FFMA is half-rate; FFMA2 is the full-rate path) ----
__device__ __forceinline__ unsigned long long pk2(float v){
  unsigned long long r; asm("mov.b64 %0, {%1, %1};" : "=l"(r) : "f"(v)); return r;
}
__device__ __forceinline__ void fma2(unsigned long long &d, unsigned long long a, unsigned long long b){
  asm("fma.rn.f32x2 %0, %1, %2, %0;" : "+l"(d) : "l"(a), "l"(b));
}
__device__ __forceinline__ float2 up2(unsigned long long v){
  float2 f; asm("mov.b64 {%0, %1}, %2;" : "=f"(f.x), "=f"(f.y) : "l"(v)); return f;
}

// ---- generic 64x64 tile GEMM body, 256 threads, 4x4 per thread, BK=16 ----
// NT:  C = scale * A(MxK,lda) * B(NxK,ldb)^T      (both K-contiguous)
// NN:  C = scale * A(MxK,lda) * B(KxN,ldb)
// All dims here are exact multiples (448 = 7*64, 4096 = 64*64, K % 16 == 0).
template<bool NT>
__device__ __forceinline__ void gemm_body(const float* __restrict__ A, const float* __restrict__ B,
                                          float* __restrict__ C, int K, int lda, int ldb, int ldc,
                                          float scale)
{
  __shared__ float As[16][68];
  __shared__ float Bs[16][68];
  const int tid = threadIdx.x;
  const int tx = tid & 15, ty = tid >> 4;
  const int m0 = blockIdx.x * 64, n0 = blockIdx.y * 64;
  unsigned long long acc[4][2];
#pragma unroll
  for (int i = 0; i < 4; i++) { acc[i][0] = 0ull; acc[i][1] = 0ull; }
  const int ra = tid >> 2, ka = tid & 3;   // NT-style loads: 64 rows x 4 float4
  const int kb = tid >> 4, nb = tid & 15;  // NN B load: 16 k-rows x 16 float4

  for (int k0 = 0; k0 < K; k0 += 16) {
    float4 av = *(const float4*)(A + (long)(m0 + ra) * lda + k0 + ka * 4);
    As[ka*4+0][ra] = av.x; As[ka*4+1][ra] = av.y; As[ka*4+2][ra] = av.z; As[ka*4+3][ra] = av.w;
    if (NT) {
      float4 bv = *(const float4*)(B + (long)(n0 + ra) * ldb + k0 + ka * 4);
      Bs[ka*4+0][ra] = bv.x; Bs[ka*4+1][ra] = bv.y; Bs[ka*4+2][ra] = bv.z; Bs[ka*4+3][ra] = bv.w;
    } else {
      *(float4*)&Bs[kb][nb*4] = *(const float4*)(B + (long)(k0 + kb) * ldb + n0 + nb * 4);
    }
    __syncthreads();
#pragma unroll
    for (int k = 0; k < 16; k++) {
      float4 a = *(const float4*)&As[k][ty*4];
      ulonglong2 bb = *(const ulonglong2*)&Bs[k][tx*4];
      unsigned long long a0 = pk2(a.x), a1 = pk2(a.y), a2 = pk2(a.z), a3 = pk2(a.w);
      fma2(acc[0][0], a0, bb.x); fma2(acc[0][1], a0, bb.y);
      fma2(acc[1][0], a1, bb.x); fma2(acc[1][1], a1, bb.y);
      fma2(acc[2][0], a2, bb.x); fma2(acc[2][1], a2, bb.y);
      fma2(acc[3][0], a3, bb.x); fma2(acc[3][1], a3, bb.y);
    }
    __syncthreads();
  }
#pragma unroll
  for (int i = 0; i < 4; i++) {
    float2 lo = up2(acc[i][0]), hi = up2(acc[i][1]);
    float4 o = make_float4(lo.x*scale, lo.y*scale, hi.x*scale, hi.y*scale);
    *(float4*)(C + (long)(m0 + ty*4 + i) * ldc + n0 + tx*4) = o;
  }
}

// Phase 1: G[z] = V_s[b] @ V_r[b']^T ; z<16 -> b'=b (pos), z>=16 -> b'=(b+1)%16 (neg)
__global__ void __launch_bounds__(256) gram_kernel(const float* __restrict__ Vs,
                                                   const float* __restrict__ Vr)
{
  int z = blockIdx.z;
  int b = z & 15;
  int b2 = (z < 16) ? b : ((b + 1) & 15);
  gemm_body<true>(Vs + (long)b  * D_ * HW_,
                  Vr + (long)b2 * D_ * HW_,
                  g_G + (long)z * DSQ, HW_, HW_, HW_, D_, 1.0f);
}

// Phase 2: T[z] = G[z] @ Wk^T  (NT, 448^3)
__global__ void __launch_bounds__(256) gkt_kernel(const float* __restrict__ Wk)
{
  int z = blockIdx.z;
  gemm_body<true>(g_G + (long)z * DSQ, Wk, g_T + (long)z * DSQ, D_, D_, D_, D_, 1.0f);
}

// Phase 3: S[z] = Wq @ T[z] / sqrt(448)  (NN)
__global__ void __launch_bounds__(256) wqt_kernel(const float* __restrict__ Wq)
{
  int z = blockIdx.z;
  const float SCALE = 0.047245559f; // 1/sqrt(448)
  gemm_body<false>(Wq, g_T + (long)z * DSQ, g_S + (long)z * DSQ, D_, D_, D_, D_, SCALE);
}

// Phase 4: row softmax of g_S in place (32*448 rows of 448). One warp per row.
__global__ void __launch_bounds__(256) softmax_kernel()
{
  int warp = (blockIdx.x * blockDim.x + threadIdx.x) >> 5;
  int lane = threadIdx.x & 31;
  if (warp >= 32 * D_) return;
  float* row = g_S + (long)warp * D_;
  float v[14];
  float mx = -1e30f;
#pragma unroll
  for (int i = 0; i < 14; i++) { v[i] = row[lane + i * 32]; mx = fmaxf(mx, v[i]); }
#pragma unroll
  for (int o = 16; o; o >>= 1) mx = fmaxf(mx, __shfl_xor_sync(0xffffffffu, mx, o));
  float s = 0.f;
#pragma unroll
  for (int i = 0; i < 14; i++) { v[i] = __expf(v[i] - mx); s += v[i]; }
#pragma unroll
  for (int o = 16; o; o >>= 1) s += __shfl_xor_sync(0xffffffffu, s, o);
  float inv = 1.0f / s;
#pragma unroll
  for (int i = 0; i < 14; i++) row[lane + i * 32] = v[i] * inv;
}

// Phase 5: A[z] = alpha[z] @ Wv  (NN)
__global__ void __launch_bounds__(256) av_kernel(const float* __restrict__ Wv)
{
  int z = blockIdx.z;
  gemm_body<false>(g_S + (long)z * DSQ, Wv, g_A + (long)z * DSQ, D_, D_, D_, D_, 1.0f);
}

// Phase 6: for each batch b, compute v_asta = A[b] @ V_r[b] and v_neg = A[16+b] @ V_r[b]
// simultaneously; out = V_s + v_asta; accumulate relu(v_neg - v_asta + 12) per block.
__global__ void __launch_bounds__(256) final_kernel(const float* __restrict__ Vr,
                                                    const float* __restrict__ Vs,
                                                    float* __restrict__ out)
{
  __shared__ float Ap[16][68];
  __shared__ float An[16][68];
  __shared__ float Bs[16][68];
  const int b = blockIdx.z;
  const float* Apos = g_A + (long)b * DSQ;
  const float* Aneg = g_A + (long)(16 + b) * DSQ;
  const float* Bm   = Vr + (long)b * D_ * HW_;
  const int tid = threadIdx.x;
  const int tx = tid & 15, ty = tid >> 4;
  const int m0 = blockIdx.x * 64, n0 = blockIdx.y * 64;
  unsigned long long accP[4][2], accN[4][2];
#pragma unroll
  for (int i = 0; i < 4; i++) { accP[i][0]=0ull; accP[i][1]=0ull; accN[i][0]=0ull; accN[i][1]=0ull; }
  const int ra = tid >> 2, ka = tid & 3;
  const int kb = tid >> 4, nb = tid & 15;

  for (int k0 = 0; k0 < D_; k0 += 16) {
    float4 av = *(const float4*)(Apos + (long)(m0 + ra) * D_ + k0 + ka * 4);
    Ap[ka*4+0][ra] = av.x; Ap[ka*4+1][ra] = av.y; Ap[ka*4+2][ra] = av.z; Ap[ka*4+3][ra] = av.w;
    float4 nv = *(const float4*)(Aneg + (long)(m0 + ra) * D_ + k0 + ka * 4);
    An[ka*4+0][ra] = nv.x; An[ka*4+1][ra] = nv.y; An[ka*4+2][ra] = nv.z; An[ka*4+3][ra] = nv.w;
    *(float4*)&Bs[kb][nb*4] = *(const float4*)(Bm + (long)(k0 + kb) * HW_ + n0 + nb * 4);
    __syncthreads();
#pragma unroll
    for (int k = 0; k < 16; k++) {
      float4 ap = *(const float4*)&Ap[k][ty*4];
      float4 an = *(const float4*)&An[k][ty*4];
      ulonglong2 bb = *(const ulonglong2*)&Bs[k][tx*4];
      unsigned long long p0 = pk2(ap.x), p1 = pk2(ap.y), p2 = pk2(ap.z), p3 = pk2(ap.w);
      unsigned long long q0 = pk2(an.x), q1 = pk2(an.y), q2 = pk2(an.z), q3 = pk2(an.w);
      fma2(accP[0][0], p0, bb.x); fma2(accP[0][1], p0, bb.y);
      fma2(accP[1][0], p1, bb.x); fma2(accP[1][1], p1, bb.y);
      fma2(accP[2][0], p2, bb.x); fma2(accP[2][1], p2, bb.y);
      fma2(accP[3][0], p3, bb.x); fma2(accP[3][1], p3, bb.y);
      fma2(accN[0][0], q0, bb.x); fma2(accN[0][1], q0, bb.y);
      fma2(accN[1][0], q1, bb.x); fma2(accN[1][1], q1, bb.y);
      fma2(accN[2][0], q2, bb.x); fma2(accN[2][1], q2, bb.y);
      fma2(accN[3][0], q3, bb.x); fma2(accN[3][1], q3, bb.y);
    }
    __syncthreads();
  }

  float lsum = 0.f;
#pragma unroll
  for (int i = 0; i < 4; i++) {
    float2 pl = up2(accP[i][0]), ph = up2(accP[i][1]);
    float2 ql = up2(accN[i][0]), qh = up2(accN[i][1]);
    long idx = ((long)b * D_ + m0 + ty*4 + i) * HW_ + n0 + tx*4;
    float4 vs = *(const float4*)(Vs + idx);
    float4 o = make_float4(vs.x + pl.x, vs.y + pl.y, vs.z + ph.x, vs.w + ph.y);
    *(float4*)(out + idx) = o;
    lsum += fmaxf(ql.x - pl.x + 12.0f, 0.0f);
    lsum += fmaxf(ql.y - pl.y + 12.0f, 0.0f);
    lsum += fmaxf(qh.x - ph.x + 12.0f, 0.0f);
    lsum += fmaxf(qh.y - ph.y + 12.0f, 0.0f);
  }
  // deterministic block reduction of loss
  __shared__ float red[256];
  red[tid] = lsum;
  __syncthreads();
  for (int s = 128; s; s >>= 1) {
    if (tid < s) red[tid] += red[tid + s];
    __syncthreads();
  }
  if (tid == 0)
    g_part[blockIdx.z * (gridDim.x * gridDim.y) + blockIdx.x * gridDim.y + blockIdx.y] = red[0];
}

// Phase 7: deterministic final loss reduction -> out[NOUT] = mean
__global__ void __launch_bounds__(256) loss_reduce(float* __restrict__ out, int out_size)
{
  __shared__ float red[256];
  int tid = threadIdx.x;
  float s = 0.f;
  for (int i = tid; i < NPART; i += 256) s += g_part[i];
  red[tid] = s;
  __syncthreads();
  for (int st = 128; st; st >>= 1) {
    if (tid < st) red[tid] += red[tid + st];
    __syncthreads();
  }
  if (tid == 0 && (long)out_size > NOUT)
    out[NOUT] = red[0] / (float)(16.0 * 448.0 * 4096.0);
}

extern "C" void kernel_launch(void* const* d_in, const int* in_sizes, int n_in,
                              void* d_out, int out_size)
{
  (void)in_sizes; (void)n_in;
  const float* V_r = (const float*)d_in[0];
  const float* V_s = (const float*)d_in[1];
  const float* W_q = (const float*)d_in[2];
  const float* W_k = (const float*)d_in[3];
  const float* W_v = (const float*)d_in[4];
  float* out = (float*)d_out;

  dim3 blk(256);
  gram_kernel  <<<dim3(7, 7, 32),  blk>>>(V_s, V_r);
  gkt_kernel   <<<dim3(7, 7, 32),  blk>>>(W_k);
  wqt_kernel   <<<dim3(7, 7, 32),  blk>>>(W_q);
  softmax_kernel<<<1792,           blk>>>();
  av_kernel    <<<dim3(7, 7, 32),  blk>>>(W_v);
  final_kernel <<<dim3(7, 64, 16), blk>>>(V_r, V_s, out);
  loss_reduce  <<<1,               blk>>>(out, out_size);
}

// round 2
// speedup vs baseline: 1.0002x; 1.0002x over previous
#include <cuda_runtime.h>

// Problem constants
#define B_   16
#define D_   448
#define HW_  4096
#define DSQ  (D_*D_)              // 200704
#define NOUT (16L*448L*4096L)     // 29360128 elements of c_i, loss at [NOUT]
#define NPART 7168                // 7*64*16 loss partials

// Scratch (module globals — allocation-free rule)
__device__ float g_G[32L*DSQ];   // gram: [0..15]=pos, [16..31]=neg
__device__ float g_T[32L*DSQ];   // G @ Wk^T
__device__ float g_S[32L*DSQ];   // scores -> alpha (in place)
__device__ float g_A[32L*DSQ];   // alpha @ Wv
__device__ float g_part[NPART];

// ---- packed fp32x2 helpers (B300: scalar FFMA is half-rate; FFMA2 is the full-rate path) ----
__device__ __forceinline__ unsigned long long pk2(float v){
  unsigned long long r; asm("mov.b64 %0, {%1, %1};" : "=l"(r) : "f"(v)); return r;
}
__device__ __forceinline__ void fma2(unsigned long long &d, unsigned long long a, unsigned long long b){
  asm("fma.rn.f32x2 %0, %1, %2, %0;" : "+l"(d) : "l"(a), "l"(b));
}
__device__ __forceinline__ float2 up2(unsigned long long v){
  float2 f; asm("mov.b64 {%0, %1}, %2;" : "=f"(f.x), "=f"(f.y) : "l"(v)); return f;
}

// ---- generic 64x64 tile GEMM body, 256 threads, 4x4 per thread, BK=16 ----
// NT:  C = scale * A(MxK,lda) * B(NxK,ldb)^T      (both K-contiguous)
// NN:  C = scale * A(MxK,lda) * B(KxN,ldb)
// All dims here are exact multiples (448 = 7*64, 4096 = 64*64, K % 16 == 0).
template<bool NT>
__device__ __forceinline__ void gemm_body(const float* __restrict__ A, const float* __restrict__ B,
                                          float* __restrict__ C, int K, int lda, int ldb, int ldc,
                                          float scale)
{
  __shared__ float As[16][68];
  __shared__ float Bs[16][68];
  const int tid = threadIdx.x;
  const int tx = tid & 15, ty = tid >> 4;
  const int m0 = blockIdx.x * 64, n0 = blockIdx.y * 64;
  unsigned long long acc[4][2];
#pragma unroll
  for (int i = 0; i < 4; i++) { acc[i][0] = 0ull; acc[i][1] = 0ull; }
  const int ra = tid >> 2, ka = tid & 3;   // NT-style loads: 64 rows x 4 float4
  const int kb = tid >> 4, nb = tid & 15;  // NN B load: 16 k-rows x 16 float4

  for (int k0 = 0; k0 < K; k0 += 16) {
    float4 av = *(const float4*)(A + (long)(m0 + ra) * lda + k0 + ka * 4);
    As[ka*4+0][ra] = av.x; As[ka*4+1][ra] = av.y; As[ka*4+2][ra] = av.z; As[ka*4+3][ra] = av.w;
    if (NT) {
      float4 bv = *(const float4*)(B + (long)(n0 + ra) * ldb + k0 + ka * 4);
      Bs[ka*4+0][ra] = bv.x; Bs[ka*4+1][ra] = bv.y; Bs[ka*4+2][ra] = bv.z; Bs[ka*4+3][ra] = bv.w;
    } else {
      *(float4*)&Bs[kb][nb*4] = *(const float4*)(B + (long)(k0 + kb) * ldb + n0 + nb * 4);
    }
    __syncthreads();
#pragma unroll
    for (int k = 0; k < 16; k++) {
      float4 a = *(const float4*)&As[k][ty*4];
      ulonglong2 bb = *(const ulonglong2*)&Bs[k][tx*4];
      unsigned long long a0 = pk2(a.x), a1 = pk2(a.y), a2 = pk2(a.z), a3 = pk2(a.w);
      fma2(acc[0][0], a0, bb.x); fma2(acc[0][1], a0, bb.y);
      fma2(acc[1][0], a1, bb.x); fma2(acc[1][1], a1, bb.y);
      fma2(acc[2][0], a2, bb.x); fma2(acc[2][1], a2, bb.y);
      fma2(acc[3][0], a3, bb.x); fma2(acc[3][1], a3, bb.y);
    }
    __syncthreads();
  }
#pragma unroll
  for (int i = 0; i < 4; i++) {
    float2 lo = up2(acc[i][0]), hi = up2(acc[i][1]);
    float4 o = make_float4(lo.x*scale, lo.y*scale, hi.x*scale, hi.y*scale);
    *(float4*)(C + (long)(m0 + ty*4 + i) * ldc + n0 + tx*4) = o;
  }
}

// Phase 1: G[z] = V_s[b] @ V_r[b']^T ; z<16 -> b'=b (pos), z>=16 -> b'=(b+1)%16 (neg)
__global__ void __launch_bounds__(256) gram_kernel(const float* __restrict__ Vs,
                                                   const float* __restrict__ Vr)
{
  int z = blockIdx.z;
  int b = z & 15;
  int b2 = (z < 16) ? b : ((b + 1) & 15);
  gemm_body<true>(Vs + (long)b  * D_ * HW_,
                  Vr + (long)b2 * D_ * HW_,
                  g_G + (long)z * DSQ, HW_, HW_, HW_, D_, 1.0f);
}

// Phase 2: T[z] = G[z] @ Wk^T  (NT, 448^3)
__global__ void __launch_bounds__(256) gkt_kernel(const float* __restrict__ Wk)
{
  int z = blockIdx.z;
  gemm_body<true>(g_G + (long)z * DSQ, Wk, g_T + (long)z * DSQ, D_, D_, D_, D_, 1.0f);
}

// Phase 3: S[z] = Wq @ T[z] / sqrt(448)  (NN)
__global__ void __launch_bounds__(256) wqt_kernel(const float* __restrict__ Wq)
{
  int z = blockIdx.z;
  const float SCALE = 0.047245559f; // 1/sqrt(448)
  gemm_body<false>(Wq, g_T + (long)z * DSQ, g_S + (long)z * DSQ, D_, D_, D_, D_, SCALE);
}

// Phase 4: row softmax of g_S in place (32*448 rows of 448). One warp per row.
__global__ void __launch_bounds__(256) softmax_kernel()
{
  int warp = (blockIdx.x * blockDim.x + threadIdx.x) >> 5;
  int lane = threadIdx.x & 31;
  if (warp >= 32 * D_) return;
  float* row = g_S + (long)warp * D_;
  float v[14];
  float mx = -1e30f;
#pragma unroll
  for (int i = 0; i < 14; i++) { v[i] = row[lane + i * 32]; mx = fmaxf(mx, v[i]); }
#pragma unroll
  for (int o = 16; o; o >>= 1) mx = fmaxf(mx, __shfl_xor_sync(0xffffffffu, mx, o));
  float s = 0.f;
#pragma unroll
  for (int i = 0; i < 14; i++) { v[i] = __expf(v[i] - mx); s += v[i]; }
#pragma unroll
  for (int o = 16; o; o >>= 1) s += __shfl_xor_sync(0xffffffffu, s, o);
  float inv = 1.0f / s;
#pragma unroll
  for (int i = 0; i < 14; i++) row[lane + i * 32] = v[i] * inv;
}

// Phase 5: A[z] = alpha[z] @ Wv  (NN)
__global__ void __launch_bounds__(256) av_kernel(const float* __restrict__ Wv)
{
  int z = blockIdx.z;
  gemm_body<false>(g_S + (long)z * DSQ, Wv, g_A + (long)z * DSQ, D_, D_, D_, D_, 1.0f);
}

// Phase 6: for each batch b, compute v_asta = A[b] @ V_r[b] and v_neg = A[16+b] @ V_r[b]
// simultaneously; out = V_s + v_asta; accumulate relu(v_neg - v_asta + 12) per block.
__global__ void __launch_bounds__(256) final_kernel(const float* __restrict__ Vr,
                                                    const float* __restrict__ Vs,
                                                    float* __restrict__ out)
{
  __shared__ float Ap[16][68];
  __shared__ float An[16][68];
  __shared__ float Bs[16][68];
  const int b = blockIdx.z;
  const float* Apos = g_A + (long)b * DSQ;
  const float* Aneg = g_A + (long)(16 + b) * DSQ;
  const float* Bm   = Vr + (long)b * D_ * HW_;
  const int tid = threadIdx.x;
  const int tx = tid & 15, ty = tid >> 4;
  const int m0 = blockIdx.x * 64, n0 = blockIdx.y * 64;
  unsigned long long accP[4][2], accN[4][2];
#pragma unroll
  for (int i = 0; i < 4; i++) { accP[i][0]=0ull; accP[i][1]=0ull; accN[i][0]=0ull; accN[i][1]=0ull; }
  const int ra = tid >> 2, ka = tid & 3;
  const int kb = tid >> 4, nb = tid & 15;

  for (int k0 = 0; k0 < D_; k0 += 16) {
    float4 av = *(const float4*)(Apos + (long)(m0 + ra) * D_ + k0 + ka * 4);
    Ap[ka*4+0][ra] = av.x; Ap[ka*4+1][ra] = av.y; Ap[ka*4+2][ra] = av.z; Ap[ka*4+3][ra] = av.w;
    float4 nv = *(const float4*)(Aneg + (long)(m0 + ra) * D_ + k0 + ka * 4);
    An[ka*4+0][ra] = nv.x; An[ka*4+1][ra] = nv.y; An[ka*4+2][ra] = nv.z; An[ka*4+3][ra] = nv.w;
    *(float4*)&Bs[kb][nb*4] = *(const float4*)(Bm + (long)(k0 + kb) * HW_ + n0 + nb * 4);
    __syncthreads();
#pragma unroll
    for (int k = 0; k < 16; k++) {
      float4 ap = *(const float4*)&Ap[k][ty*4];
      float4 an = *(const float4*)&An[k][ty*4];
      ulonglong2 bb = *(const ulonglong2*)&Bs[k][tx*4];
      unsigned long long p0 = pk2(ap.x), p1 = pk2(ap.y), p2 = pk2(ap.z), p3 = pk2(ap.w);
      unsigned long long q0 = pk2(an.x), q1 = pk2(an.y), q2 = pk2(an.z), q3 = pk2(an.w);
      fma2(accP[0][0], p0, bb.x); fma2(accP[0][1], p0, bb.y);
      fma2(accP[1][0], p1, bb.x); fma2(accP[1][1], p1, bb.y);
      fma2(accP[2][0], p2, bb.x); fma2(accP[2][1], p2, bb.y);
      fma2(accP[3][0], p3, bb.x); fma2(accP[3][1], p3, bb.y);
      fma2(accN[0][0], q0, bb.x); fma2(accN[0][1], q0, bb.y);
      fma2(accN[1][0], q1, bb.x); fma2(accN[1][1], q1, bb.y);
      fma2(accN[2][0], q2, bb.x); fma2(accN[2][1], q2, bb.y);
      fma2(accN[3][0], q3, bb.x); fma2(accN[3][1], q3, bb.y);
    }
    __syncthreads();
  }

  float lsum = 0.f;
#pragma unroll
  for (int i = 0; i < 4; i++) {
    float2 pl = up2(accP[i][0]), ph = up2(accP[i][1]);
    float2 ql = up2(accN[i][0]), qh = up2(accN[i][1]);
    long idx = ((long)b * D_ + m0 + ty*4 + i) * HW_ + n0 + tx*4;
    float4 vs = *(const float4*)(Vs + idx);
    float4 o = make_float4(vs.x + pl.x, vs.y + pl.y, vs.z + ph.x, vs.w + ph.y);
    *(float4*)(out + idx) = o;
    lsum += fmaxf(ql.x - pl.x + 12.0f, 0.0f);
    lsum += fmaxf(ql.y - pl.y + 12.0f, 0.0f);
    lsum += fmaxf(qh.x - ph.x + 12.0f, 0.0f);
    lsum += fmaxf(qh.y - ph.y + 12.0f, 0.0f);
  }
  // deterministic block reduction of loss
  __shared__ float red[256];
  red[tid] = lsum;
  __syncthreads();
  for (int s = 128; s; s >>= 1) {
    if (tid < s) red[tid] += red[tid + s];
    __syncthreads();
  }
  if (tid == 0)
    g_part[blockIdx.z * (gridDim.x * gridDim.y) + blockIdx.x * gridDim.y + blockIdx.y] = red[0];
}

// Phase 7: deterministic final loss reduction -> out[NOUT] = mean
__global__ void __launch_bounds__(256) loss_reduce(float* __restrict__ out, int out_size)
{
  __shared__ float red[256];
  int tid = threadIdx.x;
  float s = 0.f;
  for (int i = tid; i < NPART; i += 256) s += g_part[i];
  red[tid] = s;
  __syncthreads();
  for (int st = 128; st; st >>= 1) {
    if (tid < st) red[tid] += red[tid + st];
    __syncthreads();
  }
  if (tid == 0 && (long)out_size > NOUT)
    out[NOUT] = red[0] / (float)(16.0 * 448.0 * 4096.0);
}

extern "C" void kernel_launch(void* const* d_in, const int* in_sizes, int n_in,
                              void* d_out, int out_size)
{
  (void)in_sizes; (void)n_in;
  const float* V_r = (const float*)d_in[0];
  const float* V_s = (const float*)d_in[1];
  const float* W_q = (const float*)d_in[2];
  const float* W_k = (const float*)d_in[3];
  const float* W_v = (const float*)d_in[4];
  float* out = (float*)d_out;

  dim3 blk(256);
  gram_kernel  <<<dim3(7, 7, 32),  blk>>>(V_s, V_r);
  gkt_kernel   <<<dim3(7, 7, 32),  blk>>>(W_k);
  wqt_kernel   <<<dim3(7, 7, 32),  blk>>>(W_q);
  softmax_kernel<<<1792,           blk>>>();
  av_kernel    <<<dim3(7, 7, 32),  blk>>>(W_v);
  final_kernel <<<dim3(7, 64, 16), blk>>>(V_r, V_s, out);
  loss_reduce  <<<1,               blk>>>(out, out_size);
}